// round 4
// baseline (speedup 1.0000x reference)
#include <cuda_runtime.h>
#include <cuda_bf16.h>

#define NCAM 16

__global__ __launch_bounds__(256, 4)
void Projection_19713899889207_kernel(
    const float* __restrict__ pt3d,   // (3, Np) SoA: x-plane, y-plane, z-plane
    const float* __restrict__ R,      // (NC, 3, 3)
    const float* __restrict__ t,      // (NC, 3)
    const float* __restrict__ f,      // (NC, 2)
    const float* __restrict__ c,      // (NC, 2)
    float* __restrict__ out,          // (NC*Np, 2)
    int np)
{
    // Stage all camera params into shared: per camera 16 floats
    // layout: [9 x R row-major][3 x t][2 x f][2 x c]
    __shared__ float sp[NCAM * 16];
    int tid = threadIdx.x;
    if (tid < NCAM * 16) {
        int cam = tid >> 4;
        int k   = tid & 15;
        float v;
        if (k < 9)       v = R[cam * 9 + k];
        else if (k < 12) v = t[cam * 3 + (k - 9)];
        else if (k < 14) v = f[cam * 2 + (k - 12)];
        else             v = c[cam * 2 + (k - 14)];
        sp[tid] = v;
    }
    __syncthreads();

    int i = blockIdx.x * blockDim.x + tid;   // index of a group of 4 points
    int np4 = np >> 2;
    if (i >= np4) return;

    // Load 4 points' coordinates once (SoA planes), keep in registers.
    const float4 x4 = __ldg(reinterpret_cast<const float4*>(pt3d) + i);
    const float4 y4 = __ldg(reinterpret_cast<const float4*>(pt3d + np) + i);
    const float4 z4 = __ldg(reinterpret_cast<const float4*>(pt3d + 2 * (size_t)np) + i);

    const float xs[4] = {x4.x, x4.y, x4.z, x4.w};
    const float ys[4] = {y4.x, y4.y, y4.z, y4.w};
    const float zs[4] = {z4.x, z4.y, z4.z, z4.w};

    const size_t pbase = (size_t)i * 4;   // first point index of this thread

    for (int cam = 0; cam < NCAM; ++cam) {
        const float* pc = &sp[cam * 16];
        const float r00 = pc[0], r01 = pc[1], r02 = pc[2];
        const float r10 = pc[3], r11 = pc[4], r12 = pc[5];
        const float r20 = pc[6], r21 = pc[7], r22 = pc[8];
        const float t0  = pc[9], t1  = pc[10], t2 = pc[11];
        const float f0  = pc[12], f1 = pc[13];
        const float c0  = pc[14], c1 = pc[15];

        float u[4], v[4];
        #pragma unroll
        for (int j = 0; j < 4; ++j) {
            const float x = xs[j], y = ys[j], z = zs[j];
            const float X = fmaf(r00, x, fmaf(r01, y, fmaf(r02, z, t0)));
            const float Y = fmaf(r10, x, fmaf(r11, y, fmaf(r12, z, t1)));
            const float Z = fmaf(r20, x, fmaf(r21, y, fmaf(r22, z, t2)));
            const float iz = __fdividef(1.0f, Z);   // MUFU.RCP + mul, err ~2^-22
            u[j] = fmaf(X * iz, f0, c0);
            v[j] = fmaf(Y * iz, f1, c1);
        }

        // out row = cam*np + point; 4 consecutive points -> 8 consecutive floats
        float* o = out + ((size_t)cam * (size_t)np + pbase) * 2;
        const float4 s0 = make_float4(u[0], v[0], u[1], v[1]);
        const float4 s1 = make_float4(u[2], v[2], u[3], v[3]);
        // streaming stores: 256 MB output >> L2, avoid polluting cache
        __stcs(reinterpret_cast<float4*>(o),     s0);
        __stcs(reinterpret_cast<float4*>(o) + 1, s1);
    }
}

extern "C" void kernel_launch(void* const* d_in, const int* in_sizes, int n_in,
                              void* d_out, int out_size)
{
    // metadata order: pt3d (3,Np) f32, R (16,3,3) f32, t (16,3) f32,
    //                 f (16,2) f32, c (16,2) f32, mask (16,Np) i32 (unused: full visibility)
    const float* pt3d = (const float*)d_in[0];
    const float* R    = (const float*)d_in[1];
    const float* t    = (const float*)d_in[2];
    const float* f    = (const float*)d_in[3];
    const float* c    = (const float*)d_in[4];
    float* out        = (float*)d_out;

    const int np  = in_sizes[0] / 3;        // 2,000,000
    const int np4 = np / 4;                 // Np divisible by 4
    const int threads = 256;
    const int blocks  = (np4 + threads - 1) / threads;

    Projection_19713899889207_kernel<<<blocks, threads>>>(pt3d, R, t, f, c, out, np);
}

// round 5
// speedup vs baseline: 1.5260x; 1.5260x over previous
#include <cuda_runtime.h>
#include <cuda_bf16.h>

#define NCAM 16

// ---------- f32x2 packed-math helpers (sm_103a) ----------
__device__ __forceinline__ unsigned long long pk2(float a, float b) {
    unsigned long long r;
    asm("mov.b64 %0, {%1, %2};" : "=l"(r) : "f"(a), "f"(b));
    return r;
}
__device__ __forceinline__ void upk2(unsigned long long v, float& a, float& b) {
    asm("mov.b64 {%0, %1}, %2;" : "=f"(a), "=f"(b) : "l"(v));
}
__device__ __forceinline__ unsigned long long fma2(unsigned long long a,
                                                   unsigned long long b,
                                                   unsigned long long c) {
    unsigned long long d;
    asm("fma.rn.f32x2 %0, %1, %2, %3;" : "=l"(d) : "l"(a), "l"(b), "l"(c));
    return d;
}
__device__ __forceinline__ unsigned long long mul2(unsigned long long a,
                                                   unsigned long long b) {
    unsigned long long d;
    asm("mul.rn.f32x2 %0, %1, %2;" : "=l"(d) : "l"(a), "l"(b));
    return d;
}
__device__ __forceinline__ float frcp(float x) {
    float r;
    asm("rcp.approx.f32 %0, %1;" : "=f"(r) : "f"(x));
    return r;
}

// Shared param layout per camera: 16 duplicated pairs (128 B), order:
//   k = 0..8 : r00 r01 r02 r10 r11 r12 r20 r21 r22
//   k = 9..11: t0 t1 t2
//   k = 12,13: f0 f1
//   k = 14,15: c0 c1
// each stored as (v, v) so it is directly an f32x2 broadcast operand.

__global__ __launch_bounds__(256, 5)
void Projection_19713899889207_kernel(
    const float* __restrict__ pt3d,   // (3, Np) SoA
    const float* __restrict__ R,      // (NC, 3, 3)
    const float* __restrict__ t,      // (NC, 3)
    const float* __restrict__ f,      // (NC, 2)
    const float* __restrict__ c,      // (NC, 2)
    float* __restrict__ out,          // (NC*Np, 2)
    int np)
{
    __shared__ __align__(16) float sp[NCAM * 32];

    const int tid = threadIdx.x;
    // stage 512 floats with 256 threads (2 each)
    #pragma unroll
    for (int s = tid; s < NCAM * 32; s += 256) {
        const int cam = s >> 5;
        const int k   = (s & 31) >> 1;
        float v;
        if (k < 9)       v = R[cam * 9 + k];
        else if (k < 12) v = t[cam * 3 + (k - 9)];
        else if (k < 14) v = f[cam * 2 + (k - 12)];
        else             v = c[cam * 2 + (k - 14)];
        sp[s] = v;
    }
    __syncthreads();

    const int i = blockIdx.x * blockDim.x + tid;   // index of a PAIR of points
    const int np2 = np >> 1;
    if (i >= np2) return;

    // Two adjacent floats loaded as u64 == the f32x2 operand (x_j, x_{j+1}).
    const unsigned long long x01 =
        __ldg(reinterpret_cast<const unsigned long long*>(pt3d) + i);
    const unsigned long long y01 =
        __ldg(reinterpret_cast<const unsigned long long*>(pt3d + (size_t)np) + i);
    const unsigned long long z01 =
        __ldg(reinterpret_cast<const unsigned long long*>(pt3d + 2 * (size_t)np) + i);

    const size_t pbase = (size_t)i * 2;   // first point index

    #pragma unroll 1
    for (int cam = 0; cam < NCAM; ++cam) {
        const ulonglong2* Q = reinterpret_cast<const ulonglong2*>(sp + cam * 32);
        const ulonglong2 q0 = Q[0];  // (r00d, r01d)
        const ulonglong2 q1 = Q[1];  // (r02d, r10d)
        const ulonglong2 q2 = Q[2];  // (r11d, r12d)
        const ulonglong2 q3 = Q[3];  // (r20d, r21d)
        const ulonglong2 q4 = Q[4];  // (r22d, t0d)
        const ulonglong2 q5 = Q[5];  // (t1d,  t2d)
        const ulonglong2 q6 = Q[6];  // (f0d,  f1d)
        const ulonglong2 q7 = Q[7];  // (c0d,  c1d)

        // Rotation + translation, two points per packed op.
        const unsigned long long X =
            fma2(q0.x, x01, fma2(q0.y, y01, fma2(q1.x, z01, q4.y)));
        const unsigned long long Y =
            fma2(q1.y, x01, fma2(q2.x, y01, fma2(q2.y, z01, q5.x)));
        const unsigned long long Z =
            fma2(q3.x, x01, fma2(q3.y, y01, fma2(q4.x, z01, q5.y)));

        float z0, z1;
        upk2(Z, z0, z1);
        const unsigned long long IZ = pk2(frcp(z0), frcp(z1));

        const unsigned long long U = fma2(mul2(X, IZ), q6.x, q7.x);
        const unsigned long long V = fma2(mul2(Y, IZ), q6.y, q7.y);

        float u0, u1, v0, v1;
        upk2(U, u0, u1);
        upk2(V, v0, v1);

        // output rows: cam*np + pbase .. +1  -> 4 consecutive floats (u0,v0,u1,v1)
        float* o = out + ((size_t)cam * (size_t)np + pbase) * 2;
        __stcs(reinterpret_cast<float4*>(o), make_float4(u0, v0, u1, v1));
    }
}

extern "C" void kernel_launch(void* const* d_in, const int* in_sizes, int n_in,
                              void* d_out, int out_size)
{
    // metadata order: pt3d (3,Np) f32, R (16,3,3) f32, t (16,3) f32,
    //                 f (16,2) f32, c (16,2) f32, mask (16,Np) i32 (unused)
    const float* pt3d = (const float*)d_in[0];
    const float* R    = (const float*)d_in[1];
    const float* t    = (const float*)d_in[2];
    const float* f    = (const float*)d_in[3];
    const float* c    = (const float*)d_in[4];
    float* out        = (float*)d_out;

    const int np  = in_sizes[0] / 3;        // 2,000,000
    const int np2 = np / 2;
    const int threads = 256;
    const int blocks  = (np2 + threads - 1) / threads;

    Projection_19713899889207_kernel<<<blocks, threads>>>(pt3d, R, t, f, c, out, np);
}